// round 17
// baseline (speedup 1.0000x reference)
#include <cuda_runtime.h>
#include <cuda_bf16.h>

#define EPS_F 1e-7f

// Single-wave persistent variant of the converged R6 streaming kernel.
// 1024 blocks x 256 threads = 2^18 threads (7 blocks/SM -> one wave, no wave
// transitions, no launch/drain tail). Each thread runs 8 iterations of the
// proven batch-4 pattern: iteration i covers base = i*2^18 + tid, elements at
// base + j*2^21. Both strides are multiples of 1024, so the channel is
// tid & 1023 for all 32 elements -> coefficients computed once per thread.
// .cs streaming policy (measured best across the full R1-R14 matrix).
__global__ __launch_bounds__(256) void lorentz_persist_kernel(
    const float4* __restrict__ T4,
    const float*  __restrict__ Bo,
    float4* __restrict__ out4)
{
    const unsigned tid = blockIdx.x * 256u + threadIdx.x;   // 0 .. 2^18-1
    const int c = tid & 1023;

    // ---- per-channel coefficients (once per thread, 32 elements amortized) ----
    const float b0 = __ldg(&Bo[3 * c + 0]);
    const float b1 = __ldg(&Bo[3 * c + 1]);
    const float b2 = __ldg(&Bo[3 * c + 2]);
    const float m2 = fmaf(b0, b0, fmaf(b1, b1, b2 * b2));

    float n0, n1, n2, g;
    const float mag  = sqrtf(m2);
    const float magc = fminf(fmaxf(mag, EPS_F), 1.0f - EPS_F);
    if (magc == mag) {
        // fast path (always taken for this data): no clipping active
        const float inv = rsqrtf(m2);
        n0 = b0 * inv; n1 = b1 * inv; n2 = b2 * inv;
        g  = rsqrtf(1.0f - m2);
    } else {
        // exact reference semantics when mag is clipped (rare/never)
        n0 = b0 / magc; n1 = b1 / magc; n2 = b2 / magc;
        g  = rsqrtf(1.0f - magc * magc);
    }
    const float gb  = g * magc;   // g * mag
    const float gm1 = g - 1.0f;

    const unsigned ISTRIDE = 1u << 18;  // per-iteration base stride (threads)
    const unsigned JSTRIDE = 1u << 21;  // batch stride within an iteration

    for (int i = 0; i < 8; i++) {
        const unsigned base = (unsigned)i * ISTRIDE + tid;

        float4 x0 = __ldcs(&T4[base + 0u * JSTRIDE]);
        float4 x1 = __ldcs(&T4[base + 1u * JSTRIDE]);
        float4 x2 = __ldcs(&T4[base + 2u * JSTRIDE]);
        float4 x3 = __ldcs(&T4[base + 3u * JSTRIDE]);

        float4 o0, o1, o2, o3;
        {
            float dot = fmaf(n0, x0.y, fmaf(n1, x0.z, n2 * x0.w));
            float k   = fmaf(gm1, dot, -(gb * x0.x));   // (g-1)(n.v) - g*mag*t
            o0.x = fmaf(g, x0.x, -(gb * dot));          // g*t - g*mag*(n.v)
            o0.y = fmaf(n0, k, x0.y);
            o0.z = fmaf(n1, k, x0.z);
            o0.w = fmaf(n2, k, x0.w);
        }
        {
            float dot = fmaf(n0, x1.y, fmaf(n1, x1.z, n2 * x1.w));
            float k   = fmaf(gm1, dot, -(gb * x1.x));
            o1.x = fmaf(g, x1.x, -(gb * dot));
            o1.y = fmaf(n0, k, x1.y);
            o1.z = fmaf(n1, k, x1.z);
            o1.w = fmaf(n2, k, x1.w);
        }
        {
            float dot = fmaf(n0, x2.y, fmaf(n1, x2.z, n2 * x2.w));
            float k   = fmaf(gm1, dot, -(gb * x2.x));
            o2.x = fmaf(g, x2.x, -(gb * dot));
            o2.y = fmaf(n0, k, x2.y);
            o2.z = fmaf(n1, k, x2.z);
            o2.w = fmaf(n2, k, x2.w);
        }
        {
            float dot = fmaf(n0, x3.y, fmaf(n1, x3.z, n2 * x3.w));
            float k   = fmaf(gm1, dot, -(gb * x3.x));
            o3.x = fmaf(g, x3.x, -(gb * dot));
            o3.y = fmaf(n0, k, x3.y);
            o3.z = fmaf(n1, k, x3.z);
            o3.w = fmaf(n2, k, x3.w);
        }

        __stcs(&out4[base + 0u * JSTRIDE], o0);
        __stcs(&out4[base + 1u * JSTRIDE], o1);
        __stcs(&out4[base + 2u * JSTRIDE], o2);
        __stcs(&out4[base + 3u * JSTRIDE], o3);
    }
}

extern "C" void kernel_launch(void* const* d_in, const int* in_sizes, int n_in,
                              void* d_out, int out_size) {
    const float* T  = (const float*)d_in[0];   // 8192*1024*4 fp32
    const float* Bo = (const float*)d_in[1];   // 1024*3 fp32
    float* out = (float*)d_out;

    // 2^23 four-vectors; 2^18 threads x 8 iterations x 4 elements
    lorentz_persist_kernel<<<1024, 256>>>((const float4*)T, Bo, (float4*)out);
}